// round 8
// baseline (speedup 1.0000x reference)
#include <cuda_runtime.h>

// Exact integer reformulation of the PUMA crossbar MVM conv (validated R1-R7):
//   out = RNE_clip( conv_int(xi16, dw) / 4096 ) / 4096
//   xi16 = sext16(rint(x*4096)),  dw = clamp(rint(w*4096), +/-65535)
//
// R8 = R7 + single-wave occupancy fix: 512 blocks at occ 4 (592 slots) so the
// grid fits ONE wave (R7 ran 1.15 waves at occ 3 -> ~18% tail loss). Staging
// vectorized with float4 LDG. Mainloop: column-sliding, 2 ow-cols/thread,
// 72 IMAD per ci per thread, 4-way ci-split (quarter == warp), intra-warp
// shuffle combine, SMEM reduction.

namespace {
constexpr int CIN = 64, H = 16, W = 16, COUT = 128;
constexpr int L = CIN * 9;        // 576
constexpr int CO_CHUNK = 8;
constexpr int THREADS = 128;      // 8 owpair x 2 cog(4co) x 2 ohsub x 4 ci-quarter
}

__device__ __forceinline__ float rne_fix(int S) {
    int base = S >> 12;                 // floor(S/4096)
    int rem  = S - (base << 12);        // 0..4095
    if (rem > 2048)       base += 1;
    else if (rem == 2048) base += (base & 1);   // ties to even
    base = max(-32768, min(32767, base));
    return (float)base * (1.0f / 4096.0f);
}

__global__ __launch_bounds__(THREADS, 4)
void conv_mvm_kernel(const float* __restrict__ x,
                     const float* __restrict__ w,
                     float* __restrict__ out)
{
    __shared__ int  sw[L * CO_CHUNK];   // 18432 B : [l][co_local(8)]
    __shared__ int  sx[CIN * 4 * 16];   // 16384 B : [ci][r 0..3][col 0..15] sext16
    __shared__ int4 red[3][32][2];      //  3072 B : quarters 1..3 partials

    const int bid     = blockIdx.x;       // 512 = 16 chunks x 8 ohp x 4 b
    const int coChunk = bid & 15;
    const int ohp     = (bid >> 4) & 7;
    const int b       = bid >> 7;

    const int tid     = threadIdx.x;
    const int p       = tid & 7;          // ow pair -> cols 2p, 2p+1
    const int cog     = (tid >> 3) & 1;   // group of 4 Cout
    const int ohsub   = (tid >> 4) & 1;
    const int quarter = tid >> 5;         // == warp id; ci quarter

    // ---- stage weights: float4 LDG + quantize, tile layout [l][co] ----
    {
        const float4* wsrc = (const float4*)(w + coChunk * CO_CHUNK * L);
        #pragma unroll
        for (int it = 0; it < (CO_CHUNK * L / 4) / THREADS; ++it) {   // 9 iters
            int vidx = it * THREADS + tid;          // float4 index
            int idx  = vidx * 4;
            int co   = idx / L;
            int l    = idx - co * L;                // 4 consecutive l, same co
            float4 wv = wsrc[vidx];
            int q0 = max(-65535, min(65535, __float2int_rn(wv.x * 4096.0f)));
            int q1 = max(-65535, min(65535, __float2int_rn(wv.y * 4096.0f)));
            int q2 = max(-65535, min(65535, __float2int_rn(wv.z * 4096.0f)));
            int q3 = max(-65535, min(65535, __float2int_rn(wv.w * 4096.0f)));
            int* d = &sw[l * CO_CHUNK + co];
            d[0 * CO_CHUNK] = q0;
            d[1 * CO_CHUNK] = q1;
            d[2 * CO_CHUNK] = q2;
            d[3 * CO_CHUNK] = q3;
        }
    }

    // ---- stage inputs: 4 rows x 16 cols x 64 ci, float4 LDG + sext16 ----
    #pragma unroll
    for (int it = 0; it < (CIN * 4 * 16 / 4) / THREADS; ++it) {       // 8 iters
        int vidx = it * THREADS + tid;              // float4 index
        int colv = vidx & 3;                        // which 4-col group
        int r    = (vidx >> 2) & 3;
        int ci   = vidx >> 4;
        int gr   = ohp * 2 - 1 + r;
        int4 v = make_int4(0, 0, 0, 0);
        if ((unsigned)gr < (unsigned)H) {
            float4 xv = *(const float4*)&x[((b * CIN + ci) * H + gr) * W + colv * 4];
            v.x = (__float2int_rn(xv.x * 4096.0f) << 16) >> 16;
            v.y = (__float2int_rn(xv.y * 4096.0f) << 16) >> 16;
            v.z = (__float2int_rn(xv.z * 4096.0f) << 16) >> 16;
            v.w = (__float2int_rn(xv.w * 4096.0f) << 16) >> 16;
        }
        *((int4*)sx + vidx) = v;
    }
    __syncthreads();

    // ---- mainloop: 16 ci x (3 LDS.64 x + 9 LDS.128 w + 72 IMAD) ----
    int A[2][3][4] = {};
    const int ciBase = quarter * (CIN / 4);
    #pragma unroll 8
    for (int i = 0; i < CIN / 4; ++i) {
        const int ci = ciBase + i;
        const int* xp = &sx[(ci * 4 + ohsub) * 16 + p * 2];
        const int* wp = &sw[ci * 9 * CO_CHUNK + cog * 4];
        #pragma unroll
        for (int ki = 0; ki < 3; ++ki) {
            int2 xv = *(const int2*)&xp[ki * 16];    // x[row][2p], x[row][2p+1]
            #pragma unroll
            for (int kj = 0; kj < 3; ++kj) {
                int4 wv = *(const int4*)&wp[(ki * 3 + kj) * CO_CHUNK];
                A[0][kj][0] += xv.x * wv.x;  A[0][kj][1] += xv.x * wv.y;
                A[0][kj][2] += xv.x * wv.z;  A[0][kj][3] += xv.x * wv.w;
                A[1][kj][0] += xv.y * wv.x;  A[1][kj][1] += xv.y * wv.y;
                A[1][kj][2] += xv.y * wv.z;  A[1][kj][3] += xv.y * wv.w;
            }
        }
    }

    // ---- sliding-window combine across lanes (width 8 == p dimension) ----
    // out[2p]   = A[1][0](p-1) + A[0][1] + A[1][2]
    // out[2p+1] = A[0][0]      + A[1][1] + A[0][2](p+1)
    // boundary columns are pad==0, so edge terms are zeroed exactly.
    const unsigned m32 = 0xFFFFFFFFu;
    int s0[4], s1[4];
    #pragma unroll
    for (int m = 0; m < 4; ++m) {
        int up = __shfl_up_sync(m32, A[1][0][m], 1, 8);
        int dn = __shfl_down_sync(m32, A[0][2][m], 1, 8);
        if (p == 0) up = 0;
        if (p == 7) dn = 0;
        s0[m] = up + A[0][1][m] + A[1][2][m];
        s1[m] = A[0][0][m] + A[1][1][m] + dn;
    }

    // ---- reduce ci-quarters via SMEM (quarter == warp) ----
    if (quarter != 0) {
        int lane = tid & 31;
        red[quarter - 1][lane][0] = make_int4(s0[0], s0[1], s0[2], s0[3]);
        red[quarter - 1][lane][1] = make_int4(s1[0], s1[1], s1[2], s1[3]);
    }
    __syncthreads();
    if (quarter != 0) return;

    #pragma unroll
    for (int q = 0; q < 3; ++q) {
        int4 r0 = red[q][tid][0];
        int4 r1 = red[q][tid][1];
        s0[0] += r0.x; s0[1] += r0.y; s0[2] += r0.z; s0[3] += r0.w;
        s1[0] += r1.x; s1[1] += r1.y; s1[2] += r1.z; s1[3] += r1.w;
    }

    // ---- epilogue: RNE to 1/4096 grid, clip int16, STG.64 ----
    const int oh    = ohp * 2 + ohsub;
    const int coOut = coChunk * CO_CHUNK + cog * 4;
    const int ow0   = p * 2;
    #pragma unroll
    for (int m = 0; m < 4; ++m) {
        float2 o;
        o.x = rne_fix(s0[m]);
        o.y = rne_fix(s1[m]);
        *(float2*)&out[((b * COUT + coOut + m) * H + oh) * W + ow0] = o;
    }
}

extern "C" void kernel_launch(void* const* d_in, const int* in_sizes, int n_in,
                              void* d_out, int out_size) {
    const float* x = (const float*)d_in[0];
    const float* w = (const float*)d_in[1];
    // defensive: identify tensors by element count (x: 65536, w: 73728)
    if (n_in >= 2 && in_sizes[0] == 73728 && in_sizes[1] == 65536) {
        x = (const float*)d_in[1];
        w = (const float*)d_in[0];
    }
    conv_mvm_kernel<<<512, THREADS>>>(x, w, (float*)d_out);
}

// round 9
// speedup vs baseline: 1.1065x; 1.1065x over previous
#include <cuda_runtime.h>

// Exact integer reformulation of the PUMA crossbar MVM conv (validated R1-R8):
//   out = RNE_clip( conv_int(xi16, dw) / 4096 ) / 4096
//   xi16 = sext16(rint(x*4096)),  dw = clamp(rint(w*4096), +/-65535)
//
// R9: 256 blocks x 256 threads (16 warps on the busy SMs), single wave at
// occ 2. co-chunk 16, 2 ow-cols/thread, 2 output rows, 4-way ci-split
// (quarter = tid>>6, shuffle combine intra-warp width 8). x packed as short2
// in SMEM (LDS.32 + sext), reduction buffer unioned with sx. Mainloop shape
// identical to R7 (72 IMAD / ci / thread, unroll 4) -- the proven fastest.

namespace {
constexpr int CIN = 64, H = 16, W = 16, COUT = 128;
constexpr int L = CIN * 9;        // 576
constexpr int CO_CHUNK = 16;
constexpr int THREADS = 256;      // 8p x 4cog x 2ohsub x 4 ci-quarter
}

__device__ __forceinline__ float rne_fix(int S) {
    int base = S >> 12;                 // floor(S/4096)
    int rem  = S - (base << 12);        // 0..4095
    if (rem > 2048)       base += 1;
    else if (rem == 2048) base += (base & 1);   // ties to even
    base = max(-32768, min(32767, base));
    return (float)base * (1.0f / 4096.0f);
}

__global__ __launch_bounds__(THREADS, 2)
void conv_mvm_kernel(const float* __restrict__ x,
                     const float* __restrict__ w,
                     float* __restrict__ out)
{
    __shared__ int sw[L * CO_CHUNK];   // 36864 B : [l][co_local(16)]
    __shared__ int u[2048];            //  8192 B : sx (short2 packed) / red union
    // sx view : u[(ci*4 + r)*8 + p] = packed {x[2p], x[2p+1]} int16 pair
    // red view: after-mainloop barrier, u[(q-1)*64*8 + g*8 + m] partials

    const int bid     = blockIdx.x;       // 256 = 8 chunks x 8 ohp x 4 b
    const int coChunk = bid & 7;
    const int ohp     = (bid >> 3) & 7;
    const int b       = bid >> 6;

    const int tid     = threadIdx.x;
    const int p       = tid & 7;          // ow pair -> cols 2p, 2p+1
    const int cog     = (tid >> 3) & 3;   // group of 4 Cout
    const int ohsub   = (tid >> 5) & 1;
    const int quarter = tid >> 6;         // ci quarter (2 warps each)

    // ---- stage weights: coalesced LDG + quantize, tile layout [l][co] ----
    {
        const float* wsrc = w + coChunk * CO_CHUNK * L;
        #pragma unroll
        for (int it = 0; it < (CO_CHUNK * L) / THREADS; ++it) {   // 36 iters
            int idx = it * THREADS + tid;
            int co  = idx / L;
            int l   = idx - co * L;
            int q = __float2int_rn(wsrc[idx] * 4096.0f);
            q = max(-65535, min(65535, q));
            sw[l * CO_CHUNK + co] = q;
        }
    }

    // ---- stage inputs: float2 LDG, quantize, pack short2 -> STS.32 ----
    #pragma unroll
    for (int it = 0; it < 2048 / THREADS; ++it) {                 // 8 iters
        int vidx = it * THREADS + tid;
        int cp   = vidx & 7;              // column pair
        int r    = (vidx >> 3) & 3;
        int ci   = vidx >> 5;
        int gr   = ohp * 2 - 1 + r;
        int v = 0;
        if ((unsigned)gr < (unsigned)H) {
            float2 xv = *(const float2*)&x[((b * CIN + ci) * H + gr) * W + cp * 2];
            int lo = __float2int_rn(xv.x * 4096.0f) & 0xFFFF;
            int hi = __float2int_rn(xv.y * 4096.0f) & 0xFFFF;
            v = lo | (hi << 16);
        }
        u[vidx] = v;
    }
    __syncthreads();

    // ---- mainloop: 16 ci x (3 LDS.32 x + 9 LDS.128 w + 72 IMAD) ----
    int A[2][3][4] = {};
    const int ciBase = quarter * (CIN / 4);
    #pragma unroll 4
    for (int i = 0; i < CIN / 4; ++i) {
        const int ci = ciBase + i;
        const int* xp = &u[(ci * 4 + ohsub) * 8 + p];
        const int* wp = &sw[ci * 9 * CO_CHUNK + cog * 4];
        #pragma unroll
        for (int ki = 0; ki < 3; ++ki) {
            int xpk = xp[ki * 8];
            int xv0 = (xpk << 16) >> 16;             // x[row][2p]
            int xv1 = xpk >> 16;                     // x[row][2p+1]
            #pragma unroll
            for (int kj = 0; kj < 3; ++kj) {
                int4 wv = *(const int4*)&wp[(ki * 3 + kj) * CO_CHUNK];
                A[0][kj][0] += xv0 * wv.x;  A[0][kj][1] += xv0 * wv.y;
                A[0][kj][2] += xv0 * wv.z;  A[0][kj][3] += xv0 * wv.w;
                A[1][kj][0] += xv1 * wv.x;  A[1][kj][1] += xv1 * wv.y;
                A[1][kj][2] += xv1 * wv.z;  A[1][kj][3] += xv1 * wv.w;
            }
        }
    }

    // ---- sliding-window combine across lanes (width 8 == p dimension) ----
    // out[2p]   = A[1][0](p-1) + A[0][1] + A[1][2]
    // out[2p+1] = A[0][0]      + A[1][1] + A[0][2](p+1)
    // pad columns are exactly zero -> edge terms zeroed exactly.
    const unsigned m32 = 0xFFFFFFFFu;
    int s0[4], s1[4];
    #pragma unroll
    for (int m = 0; m < 4; ++m) {
        int up = __shfl_up_sync(m32, A[1][0][m], 1, 8);
        int dn = __shfl_down_sync(m32, A[0][2][m], 1, 8);
        if (p == 0) up = 0;
        if (p == 7) dn = 0;
        s0[m] = up + A[0][1][m] + A[1][2][m];
        s1[m] = A[0][0][m] + A[1][1][m] + dn;
    }

    // ---- reduce ci-quarters via SMEM (reuses u; barrier-separated) ----
    __syncthreads();                       // all sx reads done before reuse
    const int g = tid & 63;                // (p, cog, ohsub) group id
    if (quarter != 0) {
        int* dst = &u[(quarter - 1) * 512 + g * 8];
        #pragma unroll
        for (int m = 0; m < 4; ++m) { dst[m] = s0[m]; dst[4 + m] = s1[m]; }
    }
    __syncthreads();
    if (quarter != 0) return;

    #pragma unroll
    for (int q = 0; q < 3; ++q) {
        const int* src = &u[q * 512 + g * 8];
        #pragma unroll
        for (int m = 0; m < 4; ++m) { s0[m] += src[m]; s1[m] += src[4 + m]; }
    }

    // ---- epilogue: RNE to 1/4096 grid, clip int16, STG.64 ----
    const int oh    = ohp * 2 + ohsub;
    const int coOut = coChunk * CO_CHUNK + cog * 4;
    const int ow0   = p * 2;
    #pragma unroll
    for (int m = 0; m < 4; ++m) {
        float2 o;
        o.x = rne_fix(s0[m]);
        o.y = rne_fix(s1[m]);
        *(float2*)&out[((b * COUT + coOut + m) * H + oh) * W + ow0] = o;
    }
}

extern "C" void kernel_launch(void* const* d_in, const int* in_sizes, int n_in,
                              void* d_out, int out_size) {
    const float* x = (const float*)d_in[0];
    const float* w = (const float*)d_in[1];
    // defensive: identify tensors by element count (x: 65536, w: 73728)
    if (n_in >= 2 && in_sizes[0] == 73728 && in_sizes[1] == 65536) {
        x = (const float*)d_in[1];
        w = (const float*)d_in[0];
    }
    conv_mvm_kernel<<<256, THREADS>>>(x, w, (float*)d_out);
}

// round 10
// speedup vs baseline: 1.2569x; 1.1359x over previous
#include <cuda_runtime.h>

// Exact integer reformulation of the PUMA crossbar MVM conv (validated R1-R9):
//   out = RNE_clip( conv_int(xi16, dw) / 4096 ) / 4096
//   xi16 = sext16(rint(x*4096)),  dw = clamp(rint(w*4096), +/-65535)
//
// R10 = R7 + occ 4 (single wave: 512 blocks <= 592 slots) + conflict-free
// float4 x-staging from R8. w-staging kept exactly as R7 (R8's regression was
// its stride-32 STS bank conflicts, not the occupancy). Mainloop identical to
// R7: column-sliding, 2 ow-cols/thread, 72 IMAD/ci/thread, 4-way ci-split
// (quarter == warp), intra-warp shuffle combine, SMEM reduction, unroll 4.

namespace {
constexpr int CIN = 64, H = 16, W = 16, COUT = 128;
constexpr int L = CIN * 9;        // 576
constexpr int CO_CHUNK = 8;
constexpr int THREADS = 128;      // 8 owpair x 2 cog(4co) x 2 ohsub x 4 ci-quarter
}

__device__ __forceinline__ float rne_fix(int S) {
    int base = S >> 12;                 // floor(S/4096)
    int rem  = S - (base << 12);        // 0..4095
    if (rem > 2048)       base += 1;
    else if (rem == 2048) base += (base & 1);   // ties to even
    base = max(-32768, min(32767, base));
    return (float)base * (1.0f / 4096.0f);
}

__global__ __launch_bounds__(THREADS, 4)
void conv_mvm_kernel(const float* __restrict__ x,
                     const float* __restrict__ w,
                     float* __restrict__ out)
{
    __shared__ int sw[L * CO_CHUNK];   // 18432 B : [l][co_local(8)]
    __shared__ int sx[CIN * 4 * 16];   // 16384 B : [ci][r 0..3][col 0..15] sext16
    __shared__ int red[3][32][8];      //  3072 B : quarters 1..3 partials

    const int bid     = blockIdx.x;       // 512 = 16 chunks x 8 ohp x 4 b
    const int coChunk = bid & 15;
    const int ohp     = (bid >> 4) & 7;
    const int b       = bid >> 7;

    const int tid     = threadIdx.x;
    const int p       = tid & 7;          // ow pair -> cols 2p, 2p+1
    const int cog     = (tid >> 3) & 1;   // group of 4 Cout
    const int ohsub   = (tid >> 4) & 1;
    const int quarter = tid >> 5;         // == warp id; ci quarter

    // ---- stage weights: coalesced LDG + quantize, tile layout [l][co] ----
    // (R7 orientation: consecutive lanes -> consecutive l, STS stride 8 ints)
    {
        const float* wsrc = w + coChunk * CO_CHUNK * L;
        #pragma unroll
        for (int it = 0; it < (CO_CHUNK * L) / THREADS; ++it) {   // 36 iters
            int idx = it * THREADS + tid;
            int co  = idx / L;
            int l   = idx - co * L;
            int q = __float2int_rn(wsrc[idx] * 4096.0f);
            q = max(-65535, min(65535, q));
            sw[l * CO_CHUNK + co] = q;
        }
    }

    // ---- stage inputs: float4 LDG + sext16, int4 STS (conflict-free) ----
    #pragma unroll
    for (int it = 0; it < (CIN * 4 * 16 / 4) / THREADS; ++it) {   // 8 iters
        int vidx = it * THREADS + tid;              // int4 index
        int colv = vidx & 3;
        int r    = (vidx >> 2) & 3;
        int ci   = vidx >> 4;
        int gr   = ohp * 2 - 1 + r;
        int4 v = make_int4(0, 0, 0, 0);
        if ((unsigned)gr < (unsigned)H) {
            float4 xv = *(const float4*)&x[((b * CIN + ci) * H + gr) * W + colv * 4];
            v.x = (__float2int_rn(xv.x * 4096.0f) << 16) >> 16;
            v.y = (__float2int_rn(xv.y * 4096.0f) << 16) >> 16;
            v.z = (__float2int_rn(xv.z * 4096.0f) << 16) >> 16;
            v.w = (__float2int_rn(xv.w * 4096.0f) << 16) >> 16;
        }
        *((int4*)sx + vidx) = v;
    }
    __syncthreads();

    // ---- mainloop: 16 ci x (3 LDS.64 x + 9 LDS.128 w + 72 IMAD) ----
    int A[2][3][4] = {};
    const int ciBase = quarter * (CIN / 4);
    #pragma unroll 4
    for (int i = 0; i < CIN / 4; ++i) {
        const int ci = ciBase + i;
        const int* xp = &sx[(ci * 4 + ohsub) * 16 + p * 2];
        const int* wp = &sw[ci * 9 * CO_CHUNK + cog * 4];
        #pragma unroll
        for (int ki = 0; ki < 3; ++ki) {
            int2 xv = *(const int2*)&xp[ki * 16];    // x[row][2p], x[row][2p+1]
            #pragma unroll
            for (int kj = 0; kj < 3; ++kj) {
                int4 wv = *(const int4*)&wp[(ki * 3 + kj) * CO_CHUNK];
                A[0][kj][0] += xv.x * wv.x;  A[0][kj][1] += xv.x * wv.y;
                A[0][kj][2] += xv.x * wv.z;  A[0][kj][3] += xv.x * wv.w;
                A[1][kj][0] += xv.y * wv.x;  A[1][kj][1] += xv.y * wv.y;
                A[1][kj][2] += xv.y * wv.z;  A[1][kj][3] += xv.y * wv.w;
            }
        }
    }

    // ---- sliding-window combine across lanes (width 8 == p dimension) ----
    // out[2p]   = A[1][0](p-1) + A[0][1] + A[1][2]
    // out[2p+1] = A[0][0]      + A[1][1] + A[0][2](p+1)
    // pad columns are exactly zero -> edge terms zeroed exactly.
    const unsigned m32 = 0xFFFFFFFFu;
    int s0[4], s1[4];
    #pragma unroll
    for (int m = 0; m < 4; ++m) {
        int up = __shfl_up_sync(m32, A[1][0][m], 1, 8);
        int dn = __shfl_down_sync(m32, A[0][2][m], 1, 8);
        if (p == 0) up = 0;
        if (p == 7) dn = 0;
        s0[m] = up + A[0][1][m] + A[1][2][m];
        s1[m] = A[0][0][m] + A[1][1][m] + dn;
    }

    // ---- reduce ci-quarters via SMEM (quarter == warp) ----
    if (quarter != 0) {
        int lane = tid & 31;
        #pragma unroll
        for (int m = 0; m < 4; ++m) {
            red[quarter - 1][lane][m]     = s0[m];
            red[quarter - 1][lane][4 + m] = s1[m];
        }
    }
    __syncthreads();
    if (quarter != 0) return;

    #pragma unroll
    for (int q = 0; q < 3; ++q)
        #pragma unroll
        for (int m = 0; m < 4; ++m) {
            s0[m] += red[q][tid][m];
            s1[m] += red[q][tid][4 + m];
        }

    // ---- epilogue: RNE to 1/4096 grid, clip int16, STG.64 ----
    const int oh    = ohp * 2 + ohsub;
    const int coOut = coChunk * CO_CHUNK + cog * 4;
    const int ow0   = p * 2;
    #pragma unroll
    for (int m = 0; m < 4; ++m) {
        float2 o;
        o.x = rne_fix(s0[m]);
        o.y = rne_fix(s1[m]);
        *(float2*)&out[((b * COUT + coOut + m) * H + oh) * W + ow0] = o;
    }
}

extern "C" void kernel_launch(void* const* d_in, const int* in_sizes, int n_in,
                              void* d_out, int out_size) {
    const float* x = (const float*)d_in[0];
    const float* w = (const float*)d_in[1];
    // defensive: identify tensors by element count (x: 65536, w: 73728)
    if (n_in >= 2 && in_sizes[0] == 73728 && in_sizes[1] == 65536) {
        x = (const float*)d_in[1];
        w = (const float*)d_in[0];
    }
    conv_mvm_kernel<<<512, THREADS>>>(x, w, (float*)d_out);
}

// round 11
// speedup vs baseline: 1.2759x; 1.0151x over previous
#include <cuda_runtime.h>

// Exact integer reformulation of the PUMA crossbar MVM conv (validated R1-R10):
//   out = RNE_clip( conv_int(xi16, dw) / 4096 ) / 4096
//   xi16 = sext16(rint(x*4096)),  dw = clamp(rint(w*4096), +/-65535)
//
// R11 = R10 + conflict-free weight staging: lanes mapped co-major
// (co = idx&7, l = idx>>3) so each warp's 32 STS.32 hit 32 consecutive ints
// (zero bank conflicts; R10 had 8-way conflicts = ~25% of SM time in the
// pre-barrier critical path). LDG becomes 8x16B segments/warp -- L2 at 3.2%
// absorbs it. Mainloop / shuffle combine / reduction identical to R10.

namespace {
constexpr int CIN = 64, H = 16, W = 16, COUT = 128;
constexpr int L = CIN * 9;        // 576
constexpr int CO_CHUNK = 8;
constexpr int THREADS = 128;      // 8 owpair x 2 cog(4co) x 2 ohsub x 4 ci-quarter
}

__device__ __forceinline__ float rne_fix(int S) {
    int base = S >> 12;                 // floor(S/4096)
    int rem  = S - (base << 12);        // 0..4095
    if (rem > 2048)       base += 1;
    else if (rem == 2048) base += (base & 1);   // ties to even
    base = max(-32768, min(32767, base));
    return (float)base * (1.0f / 4096.0f);
}

__global__ __launch_bounds__(THREADS, 4)
void conv_mvm_kernel(const float* __restrict__ x,
                     const float* __restrict__ w,
                     float* __restrict__ out)
{
    __shared__ int sw[L * CO_CHUNK];   // 18432 B : [l][co_local(8)]
    __shared__ int sx[CIN * 4 * 16];   // 16384 B : [ci][r 0..3][col 0..15] sext16
    __shared__ int red[3][32][8];      //  3072 B : quarters 1..3 partials

    const int bid     = blockIdx.x;       // 512 = 16 chunks x 8 ohp x 4 b
    const int coChunk = bid & 15;
    const int ohp     = (bid >> 4) & 7;
    const int b       = bid >> 7;

    const int tid     = threadIdx.x;
    const int p       = tid & 7;          // ow pair -> cols 2p, 2p+1
    const int cog     = (tid >> 3) & 1;   // group of 4 Cout
    const int ohsub   = (tid >> 4) & 1;
    const int quarter = tid >> 5;         // == warp id; ci quarter

    // ---- stage weights: co-major lane mapping -> conflict-free STS ----
    // idx = it*128 + tid; co = idx & 7, l = idx >> 3. A warp's 32 lanes
    // write 32 consecutive ints of sw (zero conflicts). LDG per warp is
    // 8 segments of 16B (L2-resident after first touch).
    {
        const float* wsrc = w + coChunk * CO_CHUNK * L;
        #pragma unroll
        for (int it = 0; it < (CO_CHUNK * L) / THREADS; ++it) {   // 36 iters
            int idx = it * THREADS + tid;
            int co  = idx & 7;
            int l   = idx >> 3;
            int q = __float2int_rn(wsrc[co * L + l] * 4096.0f);
            q = max(-65535, min(65535, q));
            sw[idx] = q;                  // == sw[l * CO_CHUNK + co]
        }
    }

    // ---- stage inputs: float4 LDG + sext16, int4 STS (conflict-free) ----
    #pragma unroll
    for (int it = 0; it < (CIN * 4 * 16 / 4) / THREADS; ++it) {   // 8 iters
        int vidx = it * THREADS + tid;              // int4 index
        int colv = vidx & 3;
        int r    = (vidx >> 2) & 3;
        int ci   = vidx >> 4;
        int gr   = ohp * 2 - 1 + r;
        int4 v = make_int4(0, 0, 0, 0);
        if ((unsigned)gr < (unsigned)H) {
            float4 xv = *(const float4*)&x[((b * CIN + ci) * H + gr) * W + colv * 4];
            v.x = (__float2int_rn(xv.x * 4096.0f) << 16) >> 16;
            v.y = (__float2int_rn(xv.y * 4096.0f) << 16) >> 16;
            v.z = (__float2int_rn(xv.z * 4096.0f) << 16) >> 16;
            v.w = (__float2int_rn(xv.w * 4096.0f) << 16) >> 16;
        }
        *((int4*)sx + vidx) = v;
    }
    __syncthreads();

    // ---- mainloop: 16 ci x (3 LDS.64 x + 9 LDS.128 w + 72 IMAD) ----
    int A[2][3][4] = {};
    const int ciBase = quarter * (CIN / 4);
    #pragma unroll 4
    for (int i = 0; i < CIN / 4; ++i) {
        const int ci = ciBase + i;
        const int* xp = &sx[(ci * 4 + ohsub) * 16 + p * 2];
        const int* wp = &sw[ci * 9 * CO_CHUNK + cog * 4];
        #pragma unroll
        for (int ki = 0; ki < 3; ++ki) {
            int2 xv = *(const int2*)&xp[ki * 16];    // x[row][2p], x[row][2p+1]
            #pragma unroll
            for (int kj = 0; kj < 3; ++kj) {
                int4 wv = *(const int4*)&wp[(ki * 3 + kj) * CO_CHUNK];
                A[0][kj][0] += xv.x * wv.x;  A[0][kj][1] += xv.x * wv.y;
                A[0][kj][2] += xv.x * wv.z;  A[0][kj][3] += xv.x * wv.w;
                A[1][kj][0] += xv.y * wv.x;  A[1][kj][1] += xv.y * wv.y;
                A[1][kj][2] += xv.y * wv.z;  A[1][kj][3] += xv.y * wv.w;
            }
        }
    }

    // ---- sliding-window combine across lanes (width 8 == p dimension) ----
    // out[2p]   = A[1][0](p-1) + A[0][1] + A[1][2]
    // out[2p+1] = A[0][0]      + A[1][1] + A[0][2](p+1)
    // pad columns are exactly zero -> edge terms zeroed exactly.
    const unsigned m32 = 0xFFFFFFFFu;
    int s0[4], s1[4];
    #pragma unroll
    for (int m = 0; m < 4; ++m) {
        int up = __shfl_up_sync(m32, A[1][0][m], 1, 8);
        int dn = __shfl_down_sync(m32, A[0][2][m], 1, 8);
        if (p == 0) up = 0;
        if (p == 7) dn = 0;
        s0[m] = up + A[0][1][m] + A[1][2][m];
        s1[m] = A[0][0][m] + A[1][1][m] + dn;
    }

    // ---- reduce ci-quarters via SMEM (quarter == warp) ----
    if (quarter != 0) {
        int lane = tid & 31;
        #pragma unroll
        for (int m = 0; m < 4; ++m) {
            red[quarter - 1][lane][m]     = s0[m];
            red[quarter - 1][lane][4 + m] = s1[m];
        }
    }
    __syncthreads();
    if (quarter != 0) return;

    #pragma unroll
    for (int q = 0; q < 3; ++q)
        #pragma unroll
        for (int m = 0; m < 4; ++m) {
            s0[m] += red[q][tid][m];
            s1[m] += red[q][tid][4 + m];
        }

    // ---- epilogue: RNE to 1/4096 grid, clip int16, STG.64 ----
    const int oh    = ohp * 2 + ohsub;
    const int coOut = coChunk * CO_CHUNK + cog * 4;
    const int ow0   = p * 2;
    #pragma unroll
    for (int m = 0; m < 4; ++m) {
        float2 o;
        o.x = rne_fix(s0[m]);
        o.y = rne_fix(s1[m]);
        *(float2*)&out[((b * COUT + coOut + m) * H + oh) * W + ow0] = o;
    }
}

extern "C" void kernel_launch(void* const* d_in, const int* in_sizes, int n_in,
                              void* d_out, int out_size) {
    const float* x = (const float*)d_in[0];
    const float* w = (const float*)d_in[1];
    // defensive: identify tensors by element count (x: 65536, w: 73728)
    if (n_in >= 2 && in_sizes[0] == 73728 && in_sizes[1] == 65536) {
        x = (const float*)d_in[1];
        w = (const float*)d_in[0];
    }
    conv_mvm_kernel<<<512, THREADS>>>(x, w, (float*)d_out);
}